// round 11
// baseline (speedup 1.0000x reference)
#include <cuda_runtime.h>
#include <cuda_fp16.h>

// GCN 2-layer, CSR-gather, HMMA GEMM (R8 structure + early unscaled gemm1):
//   deg[v] = in-edge count ; dinv = rsqrt(deg+1)
//   hf = X @ W1 (fp32, unscaled)  -- starts at t=0, no graph dependency
//   hs = half(hf * dinv[row])     -- tiny scale kernel, overlaps fill
//   out[v] = relu(dinv[v]*(sum_{s->v} hs[s] + hs[v]) + b)   (fp32 accumulate)
// edge_index is int32. CSR built once, shared by both layers.

#define MAXN 100000
#define HID 64
#define NEDGE_MAX 1600000
#define SCAN_B 512

__device__ __half2 g_hsh[MAXN * 32];    // scaled GEMM output, fp16
__device__ __half2 g_h1h[MAXN * 32];    // layer-1 output, fp16
__device__ float2  g_hf [MAXN * 32];    // unscaled gemm1 output, fp32
__device__ float   g_dinv[MAXN];
__device__ int     g_deg [MAXN];
__device__ int     g_rowstart[MAXN + 1];
__device__ int     g_cursor[MAXN];
__device__ int     g_csrc[NEDGE_MAX];
__device__ int     g_bsum[256];

// ---------------------------------------------------------------------------
__global__ void deg_count_kernel(const int* __restrict__ dst, int E) {
    int i = blockIdx.x * blockDim.x + threadIdx.x;
    if (i < E) atomicAdd(&g_deg[dst[i]], 1);
}

__global__ void scan1_kernel(int n) {
    __shared__ int sm[SCAN_B];
    int tid = threadIdx.x;
    int i = blockIdx.x * SCAN_B + tid;
    int v = (i < n) ? g_deg[i] : 0;
    sm[tid] = v;
    __syncthreads();
#pragma unroll
    for (int off = 1; off < SCAN_B; off <<= 1) {
        int t = (tid >= off) ? sm[tid - off] : 0;
        __syncthreads();
        sm[tid] += t;
        __syncthreads();
    }
    if (i < n) g_rowstart[i] = sm[tid] - v;
    if (tid == SCAN_B - 1) g_bsum[blockIdx.x] = sm[tid];
}

__global__ void scan23_kernel(int n, int E, int nb) {
    __shared__ int sb[256];
    int tid = threadIdx.x;
    int v = (tid < nb) ? g_bsum[tid] : 0;
    sb[tid] = v;
    __syncthreads();
#pragma unroll
    for (int off = 1; off < 256; off <<= 1) {
        int t = (tid >= off) ? sb[tid - off] : 0;
        __syncthreads();
        sb[tid] += t;
        __syncthreads();
    }
    int excl = sb[tid] - v;
    __syncthreads();
    sb[tid] = excl;
    __syncthreads();

    int i = blockIdx.x * blockDim.x + tid;
    if (i < n) {
        int r = g_rowstart[i] + sb[i >> 9];
        g_rowstart[i] = r;
        g_cursor[i] = r;
        g_dinv[i] = rsqrtf((float)(g_deg[i] + 1));
    }
    if (i == 0) g_rowstart[n] = E;
}

__global__ void fill_kernel(const int* __restrict__ src,
                            const int* __restrict__ dst, int E) {
    int i = blockIdx.x * blockDim.x + threadIdx.x;
    if (i < E) {
        int pos = atomicAdd(&g_cursor[dst[i]], 1);
        g_csrc[pos] = src[i];
    }
}

// ---------------------------------------------------------------------------
// hs[i] = half(hf[i] * dinv[row]) — 1 thread per half2 element.
__global__ void scale_kernel(int n32) {
    int i = blockIdx.x * blockDim.x + threadIdx.x;
    if (i >= n32) return;
    float s = g_dinv[i >> 5];
    float2 v = g_hf[i];
    g_hsh[i] = __floats2half2_rn(v.x * s, v.y * s);
}

// ---------------------------------------------------------------------------
// MMA helpers
__device__ __forceinline__ void ldmA(unsigned* a, unsigned addr) {
    asm volatile("ldmatrix.sync.aligned.m8n8.x4.shared.b16 {%0,%1,%2,%3}, [%4];"
                 : "=r"(a[0]), "=r"(a[1]), "=r"(a[2]), "=r"(a[3]) : "r"(addr));
}
__device__ __forceinline__ void ldmB(unsigned* b, unsigned addr) {
    asm volatile("ldmatrix.sync.aligned.m8n8.x2.trans.shared.b16 {%0,%1}, [%2];"
                 : "=r"(b[0]), "=r"(b[1]) : "r"(addr));
}
__device__ __forceinline__ void mma16816(float* c, const unsigned* a, const unsigned* b) {
    asm volatile(
        "mma.sync.aligned.m16n8k16.row.col.f32.f16.f16.f32 "
        "{%0,%1,%2,%3}, {%4,%5,%6,%7}, {%8,%9}, {%0,%1,%2,%3};"
        : "+f"(c[0]), "+f"(c[1]), "+f"(c[2]), "+f"(c[3])
        : "r"(a[0]), "r"(a[1]), "r"(a[2]), "r"(a[3]), "r"(b[0]), "r"(b[1]));
}

// Block tile = 128 rows; warp strip = 16 rows x 64 cols (n % 16 == 0).
// FP16IN: input fp16 (layer 2) vs fp32 (layer 1).
// SCALED: multiply by dinv[row] and write fp16 (layer 2) vs raw fp32 (layer 1).
template <bool FP16IN, bool SCALED>
__global__ void gemm_mma_kernel(const void* __restrict__ Xin,
                                const float* __restrict__ W,
                                void* __restrict__ outv, int n) {
    __shared__ alignas(16) __half Xh[128][72];
    __shared__ alignas(16) __half Wh[64][72];
    int tid = threadIdx.x;

#pragma unroll
    for (int i = tid; i < 2048; i += 256) {
        int k = (i * 2) >> 6, c = (i * 2) & 63;
        float2 w2 = ((const float2*)W)[i];
        *(__half2*)&Wh[k][c] = __floats2half2_rn(w2.x, w2.y);
    }

    int tile0 = blockIdx.x * 128;
    if constexpr (!FP16IN) {
        const float4* X4 = (const float4*)Xin;
#pragma unroll
        for (int i = tid; i < 128 * 16; i += 256) {
            int r = i >> 4, c4 = i & 15;
            int row = tile0 + r;
            if (row < n) {
                float4 v = X4[(size_t)row * 16 + c4];
                __half2* p = (__half2*)&Xh[r][c4 * 4];
                p[0] = __floats2half2_rn(v.x, v.y);
                p[1] = __floats2half2_rn(v.z, v.w);
            }
        }
    } else {
        const uint2* X2 = (const uint2*)Xin;
#pragma unroll
        for (int i = tid; i < 128 * 16; i += 256) {
            int r = i >> 4, c4 = i & 15;
            int row = tile0 + r;
            if (row < n) *(uint2*)&Xh[r][c4 * 4] = X2[(size_t)row * 16 + c4];
        }
    }
    __syncthreads();

    int warp = tid >> 5, lane = tid & 31;
    int r0 = warp * 16;
    int row0 = tile0 + r0;
    if (row0 >= n) return;

    float c[8][4];
#pragma unroll
    for (int nt = 0; nt < 8; nt++)
#pragma unroll
        for (int j = 0; j < 4; j++) c[nt][j] = 0.f;

#pragma unroll
    for (int k0 = 0; k0 < 64; k0 += 16) {
        unsigned a[4];
        unsigned aAddr = (unsigned)__cvta_generic_to_shared(
            &Xh[r0 + (lane & 15)][k0 + ((lane >> 4) << 3)]);
        ldmA(a, aAddr);
        unsigned bAddr = (unsigned)__cvta_generic_to_shared(
            &Wh[k0 + (lane & 15)][0]);
#pragma unroll
        for (int nt = 0; nt < 8; nt++) {
            unsigned bf[2];
            ldmB(bf, bAddr + nt * 16);
            mma16816(c[nt], a, bf);
        }
    }

    int rowA = row0 + (lane >> 2);
    int rowB = rowA + 8;
    if constexpr (SCALED) {
        __half2* outh = (__half2*)outv;
        float sA = g_dinv[rowA];
        float sB = g_dinv[rowB];
#pragma unroll
        for (int nt = 0; nt < 8; nt++) {
            int h2 = nt * 4 + (lane & 3);
            outh[(size_t)rowA * 32 + h2] = __floats2half2_rn(c[nt][0] * sA, c[nt][1] * sA);
            outh[(size_t)rowB * 32 + h2] = __floats2half2_rn(c[nt][2] * sB, c[nt][3] * sB);
        }
    } else {
        float2* outf = (float2*)outv;
#pragma unroll
        for (int nt = 0; nt < 8; nt++) {
            int h2 = nt * 4 + (lane & 3);
            outf[(size_t)rowA * 32 + h2] = make_float2(c[nt][0], c[nt][1]);
            outf[(size_t)rowB * 32 + h2] = make_float2(c[nt][2], c[nt][3]);
        }
    }
}

// ---------------------------------------------------------------------------
// One warp per node, shuffle-broadcast gather (fp32 accumulate).
template <bool FP16OUT>
__global__ void gather_kernel(const float* __restrict__ b,
                              void* __restrict__ outv, int n) {
    int w = (blockIdx.x * blockDim.x + threadIdx.x) >> 5;
    int lane = threadIdx.x & 31;
    if (w >= n) return;
    int v = w;
    int beg = g_rowstart[v];
    int end = g_rowstart[v + 1];
    const __half2* hsh = (const __half2*)g_hsh;

    float2 bb = ((const float2*)b)[lane];
    float2 acc = __half22float2(hsh[(size_t)v * 32 + lane]);   // self term

    for (int base = beg; base < end; base += 32) {
        int cnt = end - base;
        if (cnt > 32) cnt = 32;
        int idx = (lane < cnt) ? g_csrc[base + lane] : 0;

        int t = 0;
        for (; t + 8 <= cnt; t += 8) {
            int s0 = __shfl_sync(0xffffffff, idx, t + 0);
            int s1 = __shfl_sync(0xffffffff, idx, t + 1);
            int s2 = __shfl_sync(0xffffffff, idx, t + 2);
            int s3 = __shfl_sync(0xffffffff, idx, t + 3);
            int s4 = __shfl_sync(0xffffffff, idx, t + 4);
            int s5 = __shfl_sync(0xffffffff, idx, t + 5);
            int s6 = __shfl_sync(0xffffffff, idx, t + 6);
            int s7 = __shfl_sync(0xffffffff, idx, t + 7);
            float2 a0 = __half22float2(hsh[(size_t)s0 * 32 + lane]);
            float2 a1 = __half22float2(hsh[(size_t)s1 * 32 + lane]);
            float2 a2 = __half22float2(hsh[(size_t)s2 * 32 + lane]);
            float2 a3 = __half22float2(hsh[(size_t)s3 * 32 + lane]);
            float2 a4 = __half22float2(hsh[(size_t)s4 * 32 + lane]);
            float2 a5 = __half22float2(hsh[(size_t)s5 * 32 + lane]);
            float2 a6 = __half22float2(hsh[(size_t)s6 * 32 + lane]);
            float2 a7 = __half22float2(hsh[(size_t)s7 * 32 + lane]);
            acc.x += ((a0.x + a1.x) + (a2.x + a3.x)) + ((a4.x + a5.x) + (a6.x + a7.x));
            acc.y += ((a0.y + a1.y) + (a2.y + a3.y)) + ((a4.y + a5.y) + (a6.y + a7.y));
        }
        for (; t < cnt; t++) {
            int s = __shfl_sync(0xffffffff, idx, t);
            float2 a = __half22float2(hsh[(size_t)s * 32 + lane]);
            acc.x += a.x; acc.y += a.y;
        }
    }

    float s = g_dinv[v];
    float rx = fmaxf(fmaf(s, acc.x, bb.x), 0.f);
    float ry = fmaxf(fmaf(s, acc.y, bb.y), 0.f);
    if constexpr (FP16OUT) {
        ((__half2*)outv)[(size_t)v * 32 + lane] = __floats2half2_rn(rx, ry);
    } else {
        ((float2*)outv)[(size_t)v * 32 + lane] = make_float2(rx, ry);
    }
}

// ---------------------------------------------------------------------------
extern "C" void kernel_launch(void* const* d_in, const int* in_sizes, int n_in,
                              void* d_out, int out_size) {
    const float* x  = (const float*)d_in[0];
    const int*   ei = (const int*)d_in[1];
    const float* W1 = (const float*)d_in[2];
    const float* b1 = (const float*)d_in[3];
    const float* W2 = (const float*)d_in[4];
    const float* b2 = (const float*)d_in[5];

    int n = in_sizes[0] / HID;       // 100000
    int E = in_sizes[1] / 2;         // 1600000
    const int* src = ei;
    const int* dst = ei + E;

    __half2* hsh = nullptr; cudaGetSymbolAddress((void**)&hsh, g_hsh);
    __half2* h1h = nullptr; cudaGetSymbolAddress((void**)&h1h, g_h1h);
    float2*  hf  = nullptr; cudaGetSymbolAddress((void**)&hf,  g_hf);
    int*     deg = nullptr; cudaGetSymbolAddress((void**)&deg, g_deg);

    static cudaStream_t s2 = nullptr;
    static cudaEvent_t evFork = nullptr, evScan = nullptr, evS = nullptr;
    if (s2 == nullptr) {
        cudaStreamCreateWithFlags(&s2, cudaStreamNonBlocking);
        cudaEventCreateWithFlags(&evFork, cudaEventDisableTiming);
        cudaEventCreateWithFlags(&evScan, cudaEventDisableTiming);
        cudaEventCreateWithFlags(&evS, cudaEventDisableTiming);
    }

    int nb_scan = (n + SCAN_B - 1) / SCAN_B;             // 196 (<=256)
    int gemm_blocks = (n + 127) / 128;                   // 782
    int gather_blocks = (n * 32 + 255) / 256;            // 12500
    int n32 = n * 32;

    // ---- fork at t=0: unscaled gemm1 on side stream (no graph dependency) ----
    cudaEventRecord(evFork, 0);
    cudaStreamWaitEvent(s2, evFork, 0);
    gemm_mma_kernel<false, false><<<gemm_blocks, 256, 0, s2>>>(x, W1, hf, n);

    // ---- degree + scan (main stream) ----
    cudaMemsetAsync(deg, 0, n * sizeof(int));
    deg_count_kernel<<<(E + 255) / 256, 256>>>(dst, E);
    scan1_kernel<<<nb_scan, SCAN_B>>>(n);
    scan23_kernel<<<(n + 255) / 256, 256>>>(n, E, nb_scan);
    cudaEventRecord(evScan, 0);

    // ---- side stream: scale hf -> hsh (needs dinv + gemm1), overlaps fill ----
    cudaStreamWaitEvent(s2, evScan, 0);
    scale_kernel<<<(n32 + 255) / 256, 256, 0, s2>>>(n32);
    cudaEventRecord(evS, s2);

    fill_kernel<<<(E + 255) / 256, 256>>>(src, dst, E);

    // ---- join, layer 1 gather (fp16 out), layer 2 ----
    cudaStreamWaitEvent(0, evS, 0);
    gather_kernel<true><<<gather_blocks, 256>>>(b1, h1h, n);
    gemm_mma_kernel<true, true><<<gemm_blocks, 256>>>(h1h, W2, hsh, n);
    gather_kernel<false><<<gather_blocks, 256>>>(b2, d_out, n);
}

// round 12
// speedup vs baseline: 1.0625x; 1.0625x over previous
#include <cuda_runtime.h>
#include <cuda_fp16.h>

// GCN 2-layer, CSR-gather, HMMA GEMM. R8 launch structure (139.4us) with
// cheaper head kernels (shuffle scans, vectorized deg_count).
//   deg[v] = in-edge count ; dinv = rsqrt(deg+1)
//   hs = half((X @ W) * dinv[row])     (HMMA m16n8k16, fp16 in, fp32 acc)
//   out[v] = relu(dinv[v]*(sum_{s->v} hs[s] + hs[v]) + b)   (fp32 accumulate)
// edge_index is int32. CSR built once, shared by both layers.

#define MAXN 100000
#define HID 64
#define NEDGE_MAX 1600000
#define SCAN_ELTS 2048                       // per scan1 block (512 thr x int4)
#define SCAN_NB ((MAXN + SCAN_ELTS - 1) / SCAN_ELTS)   // 49

__device__ __half2 g_hsh[MAXN * 32];    // scaled GEMM output, fp16
__device__ __half2 g_h1h[MAXN * 32];    // layer-1 output, fp16
__device__ float   g_dinv[MAXN];
__device__ int     g_deg [MAXN];
__device__ int     g_rowstart[MAXN + 1];
__device__ int     g_cursor[MAXN];
__device__ int     g_csrc[NEDGE_MAX];
__device__ int     g_bsum[64];

// ---------------------------------------------------------------------------
// 4 edges per thread (E % 4 == 0).
__global__ void deg_count_kernel(const int4* __restrict__ dst4, int E4) {
    int i = blockIdx.x * blockDim.x + threadIdx.x;
    if (i < E4) {
        int4 d = dst4[i];
        atomicAdd(&g_deg[d.x], 1);
        atomicAdd(&g_deg[d.y], 1);
        atomicAdd(&g_deg[d.z], 1);
        atomicAdd(&g_deg[d.w], 1);
    }
}

// ---- scan1: shuffle-based block exclusive scan, 4 elts/thread ---------------
// n % 4 == 0. Writes block-local exclusive prefix to rowstart; block sums
// to g_bsum.
__global__ void scan1_kernel(int n) {
    __shared__ int wsum[16];
    __shared__ int wex [16];
    int tid = threadIdx.x, bid = blockIdx.x;
    int lane = tid & 31, wid = tid >> 5;
    int i4 = bid * 512 + tid;               // int4 index
    int n4 = n >> 2;

    int4 d = make_int4(0, 0, 0, 0);
    if (i4 < n4) d = ((const int4*)g_deg)[i4];
    int s = d.x + d.y + d.z + d.w;

    int incl = s;
#pragma unroll
    for (int off = 1; off < 32; off <<= 1) {
        int t = __shfl_up_sync(0xffffffff, incl, off);
        if (lane >= off) incl += t;
    }
    if (lane == 31) wsum[wid] = incl;
    __syncthreads();

    if (tid < 16) {
        int v = wsum[tid];
        int p = v;
#pragma unroll
        for (int off = 1; off < 16; off <<= 1) {
            int t = __shfl_up_sync(0x0000ffff, p, off);
            if (tid >= off) p += t;
        }
        wex[tid] = p - v;
        if (tid == 15) g_bsum[bid] = p;
    }
    __syncthreads();

    if (i4 < n4) {
        int base = wex[wid] + (incl - s);   // block-local exclusive for elt 0
        int4 ex;
        ex.x = base;
        ex.y = base + d.x;
        ex.z = ex.y + d.y;
        ex.w = ex.z + d.z;
        ((int4*)g_rowstart)[i4] = ex;
    }
}

// ---- scan23: add block offsets; write rowstart, cursor, dinv ----------------
__global__ void scan23_kernel(int n, int E, int nb) {
    __shared__ int sb[SCAN_NB + 1];
    int tid = threadIdx.x;
    if (tid == 0) {
        int run = 0;
        for (int j = 0; j < nb; j++) { sb[j] = run; run += g_bsum[j]; }
    }
    __syncthreads();

    int i = blockIdx.x * blockDim.x + tid;
    if (i < n) {
        int r = g_rowstart[i] + sb[i / SCAN_ELTS];
        g_rowstart[i] = r;
        g_cursor[i]   = r;
        g_dinv[i]     = rsqrtf((float)(g_deg[i] + 1));
    }
    if (i == 0) g_rowstart[n] = E;
}

__global__ void fill_kernel(const int* __restrict__ src,
                            const int* __restrict__ dst, int E) {
    int i = blockIdx.x * blockDim.x + threadIdx.x;
    if (i < E) {
        int pos = atomicAdd(&g_cursor[dst[i]], 1);
        g_csrc[pos] = src[i];
    }
}

// ---------------------------------------------------------------------------
// MMA helpers
__device__ __forceinline__ void ldmA(unsigned* a, unsigned addr) {
    asm volatile("ldmatrix.sync.aligned.m8n8.x4.shared.b16 {%0,%1,%2,%3}, [%4];"
                 : "=r"(a[0]), "=r"(a[1]), "=r"(a[2]), "=r"(a[3]) : "r"(addr));
}
__device__ __forceinline__ void ldmB(unsigned* b, unsigned addr) {
    asm volatile("ldmatrix.sync.aligned.m8n8.x2.trans.shared.b16 {%0,%1}, [%2];"
                 : "=r"(b[0]), "=r"(b[1]) : "r"(addr));
}
__device__ __forceinline__ void mma16816(float* c, const unsigned* a, const unsigned* b) {
    asm volatile(
        "mma.sync.aligned.m16n8k16.row.col.f32.f16.f16.f32 "
        "{%0,%1,%2,%3}, {%4,%5,%6,%7}, {%8,%9}, {%0,%1,%2,%3};"
        : "+f"(c[0]), "+f"(c[1]), "+f"(c[2]), "+f"(c[3])
        : "r"(a[0]), "r"(a[1]), "r"(a[2]), "r"(a[3]), "r"(b[0]), "r"(b[1]));
}

// hs[row] = half((X[row] @ W) * dinv[row])
// Block tile = 128 rows; warp strip = 16 rows x 64 cols (n % 16 == 0).
template <bool FP16IN>
__global__ void gemm_mma_kernel(const void* __restrict__ Xin,
                                const float* __restrict__ W,
                                __half2* __restrict__ outh, int n) {
    __shared__ alignas(16) __half Xh[128][72];
    __shared__ alignas(16) __half Wh[64][72];
    int tid = threadIdx.x;

#pragma unroll
    for (int i = tid; i < 2048; i += 256) {
        int k = (i * 2) >> 6, c = (i * 2) & 63;
        float2 w2 = ((const float2*)W)[i];
        *(__half2*)&Wh[k][c] = __floats2half2_rn(w2.x, w2.y);
    }

    int tile0 = blockIdx.x * 128;
    if constexpr (!FP16IN) {
        const float4* X4 = (const float4*)Xin;
#pragma unroll
        for (int i = tid; i < 128 * 16; i += 256) {
            int r = i >> 4, c4 = i & 15;
            int row = tile0 + r;
            if (row < n) {
                float4 v = X4[(size_t)row * 16 + c4];
                __half2* p = (__half2*)&Xh[r][c4 * 4];
                p[0] = __floats2half2_rn(v.x, v.y);
                p[1] = __floats2half2_rn(v.z, v.w);
            }
        }
    } else {
        const uint2* X2 = (const uint2*)Xin;
#pragma unroll
        for (int i = tid; i < 128 * 16; i += 256) {
            int r = i >> 4, c4 = i & 15;
            int row = tile0 + r;
            if (row < n) *(uint2*)&Xh[r][c4 * 4] = X2[(size_t)row * 16 + c4];
        }
    }
    __syncthreads();

    int warp = tid >> 5, lane = tid & 31;
    int r0 = warp * 16;
    int row0 = tile0 + r0;
    if (row0 >= n) return;

    float c[8][4];
#pragma unroll
    for (int nt = 0; nt < 8; nt++)
#pragma unroll
        for (int j = 0; j < 4; j++) c[nt][j] = 0.f;

#pragma unroll
    for (int k0 = 0; k0 < 64; k0 += 16) {
        unsigned a[4];
        unsigned aAddr = (unsigned)__cvta_generic_to_shared(
            &Xh[r0 + (lane & 15)][k0 + ((lane >> 4) << 3)]);
        ldmA(a, aAddr);
        unsigned bAddr = (unsigned)__cvta_generic_to_shared(
            &Wh[k0 + (lane & 15)][0]);
#pragma unroll
        for (int nt = 0; nt < 8; nt++) {
            unsigned bf[2];
            ldmB(bf, bAddr + nt * 16);
            mma16816(c[nt], a, bf);
        }
    }

    int rowA = row0 + (lane >> 2);
    int rowB = rowA + 8;
    float sA = g_dinv[rowA];
    float sB = g_dinv[rowB];
#pragma unroll
    for (int nt = 0; nt < 8; nt++) {
        int h2 = nt * 4 + (lane & 3);
        outh[(size_t)rowA * 32 + h2] = __floats2half2_rn(c[nt][0] * sA, c[nt][1] * sA);
        outh[(size_t)rowB * 32 + h2] = __floats2half2_rn(c[nt][2] * sB, c[nt][3] * sB);
    }
}

// ---------------------------------------------------------------------------
// One warp per node, shuffle-broadcast gather (fp32 accumulate).
template <bool FP16OUT>
__global__ void gather_kernel(const float* __restrict__ b,
                              void* __restrict__ outv, int n) {
    int w = (blockIdx.x * blockDim.x + threadIdx.x) >> 5;
    int lane = threadIdx.x & 31;
    if (w >= n) return;
    int v = w;
    int beg = g_rowstart[v];
    int end = g_rowstart[v + 1];
    const __half2* hsh = (const __half2*)g_hsh;

    float2 bb = ((const float2*)b)[lane];
    float2 acc = __half22float2(hsh[(size_t)v * 32 + lane]);   // self term

    for (int base = beg; base < end; base += 32) {
        int cnt = end - base;
        if (cnt > 32) cnt = 32;
        int idx = (lane < cnt) ? g_csrc[base + lane] : 0;

        int t = 0;
        for (; t + 8 <= cnt; t += 8) {
            int s0 = __shfl_sync(0xffffffff, idx, t + 0);
            int s1 = __shfl_sync(0xffffffff, idx, t + 1);
            int s2 = __shfl_sync(0xffffffff, idx, t + 2);
            int s3 = __shfl_sync(0xffffffff, idx, t + 3);
            int s4 = __shfl_sync(0xffffffff, idx, t + 4);
            int s5 = __shfl_sync(0xffffffff, idx, t + 5);
            int s6 = __shfl_sync(0xffffffff, idx, t + 6);
            int s7 = __shfl_sync(0xffffffff, idx, t + 7);
            float2 a0 = __half22float2(hsh[(size_t)s0 * 32 + lane]);
            float2 a1 = __half22float2(hsh[(size_t)s1 * 32 + lane]);
            float2 a2 = __half22float2(hsh[(size_t)s2 * 32 + lane]);
            float2 a3 = __half22float2(hsh[(size_t)s3 * 32 + lane]);
            float2 a4 = __half22float2(hsh[(size_t)s4 * 32 + lane]);
            float2 a5 = __half22float2(hsh[(size_t)s5 * 32 + lane]);
            float2 a6 = __half22float2(hsh[(size_t)s6 * 32 + lane]);
            float2 a7 = __half22float2(hsh[(size_t)s7 * 32 + lane]);
            acc.x += ((a0.x + a1.x) + (a2.x + a3.x)) + ((a4.x + a5.x) + (a6.x + a7.x));
            acc.y += ((a0.y + a1.y) + (a2.y + a3.y)) + ((a4.y + a5.y) + (a6.y + a7.y));
        }
        for (; t < cnt; t++) {
            int s = __shfl_sync(0xffffffff, idx, t);
            float2 a = __half22float2(hsh[(size_t)s * 32 + lane]);
            acc.x += a.x; acc.y += a.y;
        }
    }

    float s = g_dinv[v];
    float rx = fmaxf(fmaf(s, acc.x, bb.x), 0.f);
    float ry = fmaxf(fmaf(s, acc.y, bb.y), 0.f);
    if constexpr (FP16OUT) {
        ((__half2*)outv)[(size_t)v * 32 + lane] = __floats2half2_rn(rx, ry);
    } else {
        ((float2*)outv)[(size_t)v * 32 + lane] = make_float2(rx, ry);
    }
}

// ---------------------------------------------------------------------------
extern "C" void kernel_launch(void* const* d_in, const int* in_sizes, int n_in,
                              void* d_out, int out_size) {
    const float* x  = (const float*)d_in[0];
    const int*   ei = (const int*)d_in[1];
    const float* W1 = (const float*)d_in[2];
    const float* b1 = (const float*)d_in[3];
    const float* W2 = (const float*)d_in[4];
    const float* b2 = (const float*)d_in[5];

    int n = in_sizes[0] / HID;       // 100000
    int E = in_sizes[1] / 2;         // 1600000
    const int* src = ei;
    const int* dst = ei + E;

    __half2* hsh = nullptr; cudaGetSymbolAddress((void**)&hsh, g_hsh);
    __half2* h1h = nullptr; cudaGetSymbolAddress((void**)&h1h, g_h1h);
    int*     deg = nullptr; cudaGetSymbolAddress((void**)&deg, g_deg);

    static cudaStream_t s2 = nullptr;
    static cudaEvent_t evScan = nullptr, evG1 = nullptr;
    if (s2 == nullptr) {
        cudaStreamCreateWithFlags(&s2, cudaStreamNonBlocking);
        cudaEventCreateWithFlags(&evScan, cudaEventDisableTiming);
        cudaEventCreateWithFlags(&evG1, cudaEventDisableTiming);
    }

    int E4 = E / 4;                                      // 400000
    int gemm_blocks = (n + 127) / 128;                   // 782
    int gather_blocks = (n * 32 + 255) / 256;            // 12500

    // ---- degree + scan (main stream) ----
    cudaMemsetAsync(deg, 0, n * sizeof(int));
    deg_count_kernel<<<(E4 + 255) / 256, 256>>>((const int4*)dst, E4);
    scan1_kernel<<<SCAN_NB, 512>>>(n);
    scan23_kernel<<<(n + 255) / 256, 256>>>(n, E, SCAN_NB);
    cudaEventRecord(evScan, 0);

    // ---- fork: gemm1 (needs dinv only) overlaps fill ----
    cudaStreamWaitEvent(s2, evScan, 0);
    gemm_mma_kernel<false><<<gemm_blocks, 256, 0, s2>>>(x, W1, hsh, n);
    cudaEventRecord(evG1, s2);

    fill_kernel<<<(E + 255) / 256, 256>>>(src, dst, E);

    // ---- join, layer 1 gather (fp16 out), layer 2 ----
    cudaStreamWaitEvent(0, evG1, 0);
    gather_kernel<true><<<gather_blocks, 256>>>(b1, h1h, n);
    gemm_mma_kernel<true><<<gemm_blocks, 256>>>(h1h, W2, hsh, n);
    gather_kernel<false><<<gather_blocks, 256>>>(b2, d_out, n);
}